// round 6
// baseline (speedup 1.0000x reference)
#include <cuda_runtime.h>
#include <math.h>
#include <cstdint>

#define BD   1024
#define HD   512
#define TENC 384
#define TDEC 128
#define ID   128
#define NBLK 128
#define NTHR 256

#define ROWB 80            // smem row stride bytes (16 floats + 16B pad)
#define STB  20480         // stage bytes: A 10240 + B 10240
#define NST  4

// ---------------- static device scratch ------------------------------------
__device__ __align__(16) float g_h01[BD * 1024];   // [h0 | h1], row stride 1024
__device__ __align__(16) float g_c0 [BD * HD];
__device__ __align__(16) float g_c1 [BD * HD];
__device__ __align__(16) float g_din[BD * ID];
// tf32-pre-rounded weight copies
__device__ __align__(16) float g_rWih0[2048 * 128];
__device__ __align__(16) float g_rWhh0[2048 * 512];
__device__ __align__(16) float g_rWih1[2048 * 512];
__device__ __align__(16) float g_rWhh1[2048 * 512];
__device__ unsigned          g_bar_cnt;
__device__ volatile unsigned g_bar_gen;

// ---------------- helpers --------------------------------------------------
__device__ __forceinline__ uint32_t smem_u32(const void* p) {
    uint32_t a;
    asm("{ .reg .u64 t; cvta.to.shared.u64 t, %1; cvt.u32.u64 %0, t; }"
        : "=r"(a) : "l"(p));
    return a;
}
__device__ __forceinline__ float f2tf(float f) {
    unsigned u;
    asm("cvt.rna.tf32.f32 %0, %1;" : "=r"(u) : "f"(f));
    return __uint_as_float(u);
}
__device__ __forceinline__ float sigf(float x) {
    return __fdividef(1.f, 1.f + __expf(-x));
}
__device__ __forceinline__ float tanh_(float x) {
    float e = __expf(-2.f * fabsf(x));
    float t = __fdividef(1.f - e, 1.f + e);
    return copysignf(t, x);
}
__device__ __forceinline__ void cp16(uint32_t dst, const float* src) {
    asm volatile("cp.async.cg.shared.global [%0], [%1], 16;"
                 :: "r"(dst), "l"(src) : "memory");
}
__device__ __forceinline__ void mma8(float* c, uint32_t a0, uint32_t a1,
                                     uint32_t a2, uint32_t a3,
                                     uint32_t b0, uint32_t b1) {
    asm volatile("mma.sync.aligned.m16n8k8.row.col.f32.tf32.tf32.f32 "
                 "{%0,%1,%2,%3}, {%4,%5,%6,%7}, {%8,%9}, {%0,%1,%2,%3};"
                 : "+f"(c[0]), "+f"(c[1]), "+f"(c[2]), "+f"(c[3])
                 : "r"(a0), "r"(a1), "r"(a2), "r"(a3), "r"(b0), "r"(b1));
}
#define LDSM4(r, a)                                                          \
    asm volatile("ldmatrix.sync.aligned.m8n8.x4.shared.b16 {%0,%1,%2,%3}, [%4];" \
        : "=r"((r)[0]), "=r"((r)[1]), "=r"((r)[2]), "=r"((r)[3]) : "r"(a))

// ---------------- grid barrier ---------------------------------------------
__device__ __forceinline__ void gridbar() {
    __syncthreads();
    if (threadIdx.x == 0) {
        unsigned gen = g_bar_gen;
        __threadfence();
        if (atomicAdd(&g_bar_cnt, 1u) == NBLK - 1u) {
            g_bar_cnt = 0u;
            __threadfence();
            g_bar_gen = gen + 1u;
        } else {
            while (g_bar_gen == gen) { __nanosleep(32); }
        }
        __threadfence();
    }
    __syncthreads();
}

// ---------------- init: states, din seed, weight rounding -------------------
__device__ void init_phase(const float* __restrict__ x,
                           const float* __restrict__ Wih0,
                           const float* __restrict__ Whh0,
                           const float* __restrict__ Wih1,
                           const float* __restrict__ Whh1)
{
    const int g = blockIdx.x * NTHR + threadIdx.x;  // 0..32767
    const int GT = NBLK * NTHR;
#pragma unroll
    for (int i = 0; i < 32; i++) g_h01[g + i * GT] = 0.f;
#pragma unroll
    for (int i = 0; i < 16; i++) { g_c0[g + i * GT] = 0.f; g_c1[g + i * GT] = 0.f; }
#pragma unroll
    for (int i = 0; i < 4; i++) {
        int idx = g + i * GT;
        int b = idx >> 7, col = idx & 127;
        g_din[idx] = f2tf(x[(size_t)b * (TENC * ID) + (size_t)(TENC - 1) * ID + col]);
    }
    for (int i = g; i < 2048 * 128; i += GT) g_rWih0[i] = f2tf(Wih0[i]);
    for (int i = g; i < 2048 * 512; i += GT) {
        g_rWhh0[i] = f2tf(Whh0[i]);
        g_rWih1[i] = f2tf(Wih1[i]);
        g_rWhh1[i] = f2tf(Whh1[i]);
    }
}

// ---------------- fused GEMM + gates phase ----------------------------------
// CTA tile: 128 batch rows x 128 gate cols ({i,f,g,o} x 32 j at j0).
__device__ void phase_layer(char* smem, float* sbias,
                            const float* A1, size_t lda1, int KA1,
                            const float* A2, int lda2,
                            const float* W1, int ldw1, int KW1,
                            const float* W2, int ldw2,
                            const float* bih, const float* bhh,
                            float* cbuf, float* hdst, int KT)
{
    const int tid = threadIdx.x;
    const int m0 = (blockIdx.x >> 4) * 128;
    const int j0 = (blockIdx.x & 15) * 32;
    const int nch = KT >> 4;             // #k16 tiles

    if (tid < 128) {
        int n = (tid >> 5) * 512 + j0 + (tid & 31);
        sbias[tid] = bih[n] + bhh[n];
    }

    // -------- loader mapping: threads 0-127 load A rows, 128-255 load B rows
    const bool isA = tid < 128;
    const int  lt  = tid & 127;
    const uint32_t srow = smem_u32(smem) + (isA ? 0u : 10240u) + (uint32_t)lt * ROWB;
    const int nrow = (lt >> 5) * 512 + j0 + (lt & 31);   // weight row (B side)

    auto load_stage = [&](int ch) {
        int st = ch & (NST - 1);
        int k0 = ch * 16;
        const float* src;
        if (isA) src = (k0 < KA1) ? A1 + (size_t)(m0 + lt) * lda1 + k0
                                  : A2 + (size_t)(m0 + lt) * lda2 + (k0 - KA1);
        else     src = (k0 < KW1) ? W1 + (size_t)nrow * ldw1 + k0
                                  : W2 + (size_t)nrow * ldw2 + (k0 - KW1);
        uint32_t dst = srow + (uint32_t)st * STB;
        cp16(dst,      src);
        cp16(dst + 16, src + 4);
        cp16(dst + 32, src + 8);
        cp16(dst + 48, src + 12);
        asm volatile("cp.async.commit_group;" ::: "memory");
    };

    // -------- fragment addressing
    const int lane = tid & 31, warp = tid >> 5;
    const int wm = (warp >> 2) * 64;     // 2 m-warps
    const int wn = (warp & 3) * 32;      // 4 n-warps
    const uint32_t sA = smem_u32(smem);
    const uint32_t sB = sA + 10240;
    // A x4: tile t=lane>>3 -> rows (t&1)*8+(lane&7), unit t>>1
    const uint32_t offA = sA + (uint32_t)((((lane >> 3) & 1) * 8 + (lane & 7)) * ROWB)
                             + (uint32_t)((lane >> 4) * 16) + (uint32_t)wm * ROWB;
    // B x4: tile t=lane>>3 -> row lane&7, unit t
    const uint32_t offB = sB + (uint32_t)((lane & 7) * ROWB)
                             + (uint32_t)((lane >> 3) * 16) + (uint32_t)wn * ROWB;

    float acc[4][4][4];
#pragma unroll
    for (int mi = 0; mi < 4; mi++)
#pragma unroll
        for (int ni = 0; ni < 4; ni++)
#pragma unroll
            for (int r = 0; r < 4; r++) acc[mi][ni][r] = 0.f;

    // prologue
    load_stage(0); load_stage(1); load_stage(2);

    for (int ch = 0; ch < nch; ch++) {
        if (ch + 2 < nch)      asm volatile("cp.async.wait_group 2;" ::: "memory");
        else if (ch + 1 < nch) asm volatile("cp.async.wait_group 1;" ::: "memory");
        else                   asm volatile("cp.async.wait_group 0;" ::: "memory");
        __syncthreads();
        if (ch + 3 < nch) load_stage(ch + 3);

        const uint32_t so = (uint32_t)(ch & (NST - 1)) * STB;
        uint32_t fb[4][4];
#pragma unroll
        for (int ni = 0; ni < 4; ni++)
            LDSM4(fb[ni], offB + so + (uint32_t)(ni * 8 * ROWB));
#pragma unroll
        for (int mi = 0; mi < 4; mi++) {
            uint32_t fa0[4], fa1[4];
            LDSM4(fa0, offA + so + (uint32_t)(mi * 16 * ROWB));
            LDSM4(fa1, offA + so + (uint32_t)(mi * 16 * ROWB) + 32u);
#pragma unroll
            for (int ni = 0; ni < 4; ni++) {
                mma8(acc[mi][ni], fa0[0], fa0[1], fa0[2], fa0[3], fb[ni][0], fb[ni][1]);
                mma8(acc[mi][ni], fa1[0], fa1[1], fa1[2], fa1[3], fb[ni][2], fb[ni][3]);
            }
        }
    }

    // -------- epilogue: accs -> smem z-buffer, then gates
    float* zb = (float*)smem;            // 128 rows x 132 floats (67.6 KB)
    __syncthreads();
    {
        const int gid = lane >> 2, t4 = lane & 3;
#pragma unroll
        for (int mi = 0; mi < 4; mi++) {
            int r0 = wm + mi * 16 + gid;
#pragma unroll
            for (int ni = 0; ni < 4; ni++) {
                int c = wn + ni * 8 + t4 * 2;
                *(float2*)&zb[(size_t)r0 * 132 + c]       = make_float2(acc[mi][ni][0], acc[mi][ni][1]);
                *(float2*)&zb[(size_t)(r0 + 8) * 132 + c] = make_float2(acc[mi][ni][2], acc[mi][ni][3]);
            }
        }
    }
    __syncthreads();
    {
        const int j = lane;              // 0..31
        const float bi = sbias[j], bf = sbias[32 + j],
                    bg = sbias[64 + j], bo = sbias[96 + j];
#pragma unroll 4
        for (int rr = 0; rr < 16; rr++) {
            int row = warp * 16 + rr;
            int m   = m0 + row;
            const float* zr = zb + (size_t)row * 132;
            float zi = zr[j]      + bi;
            float zf = zr[32 + j] + bf;
            float zg = zr[64 + j] + bg;
            float zo = zr[96 + j] + bo;
            float* cp_ = cbuf + (size_t)m * HD + j0 + j;
            float c = sigf(zf) * (*cp_) + sigf(zi) * tanh_(zg);
            *cp_ = c;
            hdst[(size_t)m * 1024 + j0 + j] = f2tf(sigf(zo) * tanh_(c));
        }
    }
    __syncthreads();
}

// ---------------- fc phase (decoder projection), 32x32 tiles -----------------
__device__ void fc_phase(char* smem, const float* __restrict__ fcw,
                         const float* __restrict__ fcb,
                         float* __restrict__ out, int t)
{
    const int m0 = (blockIdx.x >> 2) * 32;     // 32 batch rows
    const int c0 = (blockIdx.x & 3) * 32;      // 32 out cols
    const int tid = threadIdx.x;
    float* hs = (float*)smem;                  // 32 x 136 floats

    const int r  = tid >> 3;                   // 0..31 output row
    const int cq = c0 + (tid & 7) * 4;         // 4 output cols
    float a0 = 0.f, a1 = 0.f, a2 = 0.f, a3 = 0.f;

    for (int kc = 0; kc < HD; kc += 128) {
        __syncthreads();
        {   // load h tile 32 x 128
            int rr = tid >> 3, u = tid & 7;
            const float4* src = (const float4*)(g_h01 + (size_t)(m0 + rr) * 1024 + 512 + kc + u * 16);
            float4* dst = (float4*)(hs + (size_t)rr * 136 + u * 16);
#pragma unroll
            for (int q = 0; q < 4; q++) dst[q] = src[q];
        }
        __syncthreads();
        const float* hr = hs + (size_t)r * 136;
        const float4* w0 = (const float4*)(fcw + (size_t)(cq + 0) * HD + kc);
        const float4* w1 = (const float4*)(fcw + (size_t)(cq + 1) * HD + kc);
        const float4* w2 = (const float4*)(fcw + (size_t)(cq + 2) * HD + kc);
        const float4* w3 = (const float4*)(fcw + (size_t)(cq + 3) * HD + kc);
#pragma unroll 8
        for (int k4 = 0; k4 < 32; k4++) {
            float4 h4 = *(const float4*)(hr + k4 * 4);
            float4 v0 = __ldg(w0 + k4), v1 = __ldg(w1 + k4);
            float4 v2 = __ldg(w2 + k4), v3 = __ldg(w3 + k4);
            a0 += h4.x * v0.x + h4.y * v0.y + h4.z * v0.z + h4.w * v0.w;
            a1 += h4.x * v1.x + h4.y * v1.y + h4.z * v1.z + h4.w * v1.w;
            a2 += h4.x * v2.x + h4.y * v2.y + h4.z * v2.z + h4.w * v2.w;
            a3 += h4.x * v3.x + h4.y * v3.y + h4.z * v3.z + h4.w * v3.w;
        }
    }
    float4 res = make_float4(a0 + fcb[cq], a1 + fcb[cq + 1],
                             a2 + fcb[cq + 2], a3 + fcb[cq + 3]);
    *(float4*)(out + (size_t)(m0 + r) * (TDEC * ID) + (size_t)t * ID + cq) = res;
    float4 dv = make_float4(f2tf(res.x), f2tf(res.y), f2tf(res.z), f2tf(res.w));
    *(float4*)(g_din + (size_t)(m0 + r) * ID + cq) = dv;
    __syncthreads();
}

// ---------------- persistent kernel -----------------------------------------
__global__ void __launch_bounds__(NTHR, 1)
lstm_persistent(const float* __restrict__ x,
                const float* __restrict__ Wih0, const float* __restrict__ Whh0,
                const float* __restrict__ bih0, const float* __restrict__ bhh0,
                const float* __restrict__ Wih1, const float* __restrict__ Whh1,
                const float* __restrict__ bih1, const float* __restrict__ bhh1,
                const float* __restrict__ fcw,  const float* __restrict__ fcb,
                float* __restrict__ out)
{
    extern __shared__ char dyn[];        // NST * STB = 81920 B
    __shared__ float s_bias[128];

    init_phase(x, Wih0, Whh0, Wih1, Whh1);
    gridbar();

    for (int t = 0; t < TENC; t++) {
        phase_layer(dyn, s_bias,
                    x + (size_t)t * ID, (size_t)TENC * ID, 128, g_h01, 1024,
                    g_rWih0, 128, 128, g_rWhh0, 512,
                    bih0, bhh0, g_c0, g_h01, 640);
        gridbar();
        phase_layer(dyn, s_bias,
                    g_h01, 1024, 512, g_h01 + 512, 1024,
                    g_rWih1, 512, 512, g_rWhh1, 512,
                    bih1, bhh1, g_c1, g_h01 + 512, 1024);
        gridbar();
    }

    for (int t = 0; t < TDEC; t++) {
        phase_layer(dyn, s_bias,
                    g_din, ID, 128, g_h01, 1024,
                    g_rWih0, 128, 128, g_rWhh0, 512,
                    bih0, bhh0, g_c0, g_h01, 640);
        gridbar();
        phase_layer(dyn, s_bias,
                    g_h01, 1024, 512, g_h01 + 512, 1024,
                    g_rWih1, 512, 512, g_rWhh1, 512,
                    bih1, bhh1, g_c1, g_h01 + 512, 1024);
        gridbar();
        fc_phase(dyn, fcw, fcb, out, t);
        gridbar();
    }
}

// ---------------- entry ------------------------------------------------------
extern "C" void kernel_launch(void* const* d_in, const int* in_sizes, int n_in,
                              void* d_out, int out_size)
{
    const int smem = NST * STB;          // 81920
    cudaFuncSetAttribute(lstm_persistent,
                         cudaFuncAttributeMaxDynamicSharedMemorySize, smem);
    lstm_persistent<<<NBLK, NTHR, smem>>>(
        (const float*)d_in[0],
        (const float*)d_in[1], (const float*)d_in[2],
        (const float*)d_in[3], (const float*)d_in[4],
        (const float*)d_in[5], (const float*)d_in[6],
        (const float*)d_in[7], (const float*)d_in[8],
        (const float*)d_in[9], (const float*)d_in[10],
        (float*)d_out);
}